// round 14
// baseline (speedup 1.0000x reference)
#include <cuda_runtime.h>
#include <cuda_fp16.h>

// Problem constants
#define NB 4096
#define NT 512
#define NC 4
#define NH 32
#define NO 3

// One warp = TWO independent 16-row MMA tiles (32 batch rows).
#define TILES 2
#define ROWS_PER_WARP 32
#define NBLOCKS (NB / ROWS_PER_WARP)   // 128

__device__ __forceinline__ unsigned h2u(float lo, float hi) {
    __half2 h = __floats2half2_rn(lo, hi);   // x = lo half, y = hi half
    return *reinterpret_cast<unsigned*>(&h);
}
__device__ __forceinline__ float h2lo(unsigned u) {
    __half2 h = *reinterpret_cast<__half2*>(&u);
    return __low2float(h);
}
__device__ __forceinline__ float h2hi(unsigned u) {
    __half2 h = *reinterpret_cast<__half2*>(&u);
    return __high2float(h);
}

// D = A*B + D   (m16n8k16, f16 inputs, f32 accumulate)
__device__ __forceinline__ void mma_acc(float& d0, float& d1, float& d2, float& d3,
                                        unsigned a0, unsigned a1, unsigned a2, unsigned a3,
                                        unsigned b0, unsigned b1) {
    asm volatile(
        "mma.sync.aligned.m16n8k16.row.col.f32.f16.f16.f32 "
        "{%0,%1,%2,%3}, {%4,%5,%6,%7}, {%8,%9}, {%0,%1,%2,%3};"
        : "+f"(d0), "+f"(d1), "+f"(d2), "+f"(d3)
        : "r"(a0), "r"(a1), "r"(a2), "r"(a3), "r"(b0), "r"(b1));
}
// D = A*B  (C = 0)
__device__ __forceinline__ void mma_zro(float& d0, float& d1, float& d2, float& d3,
                                        unsigned a0, unsigned a1, unsigned a2, unsigned a3,
                                        unsigned b0, unsigned b1) {
    asm volatile(
        "mma.sync.aligned.m16n8k16.row.col.f32.f16.f16.f32 "
        "{%0,%1,%2,%3}, {%4,%5,%6,%7}, {%8,%9}, {%10,%10,%10,%10};"
        : "=f"(d0), "=f"(d1), "=f"(d2), "=f"(d3)
        : "r"(a0), "r"(a1), "r"(a2), "r"(a3), "r"(b0), "r"(b1), "f"(0.0f));
}

__global__ void __launch_bounds__(32)
rnn_mma_kernel(const float* __restrict__ seq,
               const float* __restrict__ w_ih,
               const float* __restrict__ w_hh,
               const float* __restrict__ b_ih,
               const float* __restrict__ b_hh,
               const float* __restrict__ fc_w,
               const float* __restrict__ fc_b,
               float* __restrict__ out) {
    const int tid = threadIdx.x;
    const int gr  = tid >> 2;            // 0..7 (row group)
    const int c   = tid & 3;             // 0..3 (col group)
    const int rowbase = blockIdx.x * ROWS_PER_WARP;
    const bool lt2 = (c < 2);

    // ---- B fragments for W_hh^T (k=hidden-in, n=hidden-out), hi/lo split ----
    // SHARED by both tiles.
    unsigned bhh_hi[2][4][2], bhh_lo[2][4][2];
#pragma unroll
    for (int kc = 0; kc < 2; kc++) {
#pragma unroll
        for (int nt = 0; nt < 4; nt++) {
            const int n  = 8 * nt + gr;
            const int k0 = 16 * kc + 2 * c;
            float w[4] = { w_hh[n * NH + k0],     w_hh[n * NH + k0 + 1],
                           w_hh[n * NH + k0 + 8], w_hh[n * NH + k0 + 9] };
            float wh[4], wl[4];
#pragma unroll
            for (int i = 0; i < 4; i++) {
                wh[i] = __half2float(__float2half_rn(w[i]));
                wl[i] = w[i] - wh[i];
            }
            bhh_hi[kc][nt][0] = h2u(wh[0], wh[1]);
            bhh_hi[kc][nt][1] = h2u(wh[2], wh[3]);
            bhh_lo[kc][nt][0] = h2u(wl[0], wl[1]);
            bhh_lo[kc][nt][1] = h2u(wl[2], wl[3]);
        }
    }

    // ---- B fragments for x_proj: k-rows 0..3 = w_ih^T, k-row 4 = bias ----
    unsigned bih_hi[4], bih_lo[4];
#pragma unroll
    for (int nt = 0; nt < 4; nt++) {
        const int n = 8 * nt + gr;
        float v[2];
#pragma unroll
        for (int i = 0; i < 2; i++) {
            const int k = 2 * c + i;
            v[i] = (k < NC) ? w_ih[n * NC + k]
                            : ((k == NC) ? (b_ih[n] + b_hh[n]) : 0.0f);
        }
        const float vh0 = __half2float(__float2half_rn(v[0]));
        const float vh1 = __half2float(__float2half_rn(v[1]));
        bih_hi[nt] = h2u(vh0, vh1);
        bih_lo[nt] = h2u(v[0] - vh0, v[1] - vh1);
    }
    const unsigned zero_b = 0u;
    // seq A-frag constant for c>=2: A-col 4 = 1.0 (bias multiplier), rest 0
    const unsigned aconst = (c == 2) ? h2u(1.0f, 0.0f) : 0u;

    // Per-tile state --------------------------------------------------------
    const float2* pA[TILES];
    const float2* pB[TILES];
    float2 sA0[TILES], sB0[TILES], sA1[TILES], sB1[TILES];
    unsigned ahi[TILES][2][4], alo[TILES][2][4];
    float d0[TILES][4], d1[TILES][4], d2[TILES][4], d3[TILES][4];
    const float2 f2z = make_float2(0.f, 0.f);

#pragma unroll
    for (int tl = 0; tl < TILES; tl++) {
        const int rA = rowbase + 16 * tl + gr;
        const int rB = rA + 8;
        pA[tl] = reinterpret_cast<const float2*>(seq + (size_t)rA * (NT * NC));
        pB[tl] = reinterpret_cast<const float2*>(seq + (size_t)rB * (NT * NC));
        sA0[tl] = lt2 ? pA[tl][c]     : f2z;
        sB0[tl] = lt2 ? pB[tl][c]     : f2z;
        sA1[tl] = lt2 ? pA[tl][2 + c] : f2z;
        sB1[tl] = lt2 ? pB[tl][2 + c] : f2z;
#pragma unroll
        for (int kc = 0; kc < 2; kc++)
#pragma unroll
            for (int i = 0; i < 4; i++) {
                ahi[tl][kc][i] = 0u;
                alo[tl][kc][i] = 0u;
            }
    }

    for (int t = 0; t < NT; t++) {
        unsigned as0[TILES], as1[TILES];
        const int tn = (t + 2 < NT) ? (t + 2) : (NT - 1);
#pragma unroll
        for (int tl = 0; tl < TILES; tl++) {
            const float2 cA = sA0[tl];  sA0[tl] = sA1[tl];
            const float2 cB = sB0[tl];  sB0[tl] = sB1[tl];
            sA1[tl] = lt2 ? pA[tl][2 * tn + c] : f2z;
            sB1[tl] = lt2 ? pB[tl][2 * tn + c] : f2z;
            as0[tl] = lt2 ? h2u(cA.x, cA.y) : aconst;
            as1[tl] = lt2 ? h2u(cB.x, cB.y) : aconst;
        }

        // Single chain per accumulator (R11-winning order), tiles interleaved:
        // zro(ih_hi) -> ih_lo -> ahi*bhi(kc0,kc1) -> alo*bhi(kc0,kc1)
        //            -> ahi*blo(kc0,kc1)
#pragma unroll
        for (int nt = 0; nt < 4; nt++)
#pragma unroll
            for (int tl = 0; tl < TILES; tl++)
                mma_zro(d0[tl][nt], d1[tl][nt], d2[tl][nt], d3[tl][nt],
                        as0[tl], as1[tl], 0u, 0u, bih_hi[nt], zero_b);
#pragma unroll
        for (int nt = 0; nt < 4; nt++)
#pragma unroll
            for (int tl = 0; tl < TILES; tl++)
                mma_acc(d0[tl][nt], d1[tl][nt], d2[tl][nt], d3[tl][nt],
                        as0[tl], as1[tl], 0u, 0u, bih_lo[nt], zero_b);
#pragma unroll
        for (int kc = 0; kc < 2; kc++)
#pragma unroll
            for (int nt = 0; nt < 4; nt++)
#pragma unroll
                for (int tl = 0; tl < TILES; tl++)
                    mma_acc(d0[tl][nt], d1[tl][nt], d2[tl][nt], d3[tl][nt],
                            ahi[tl][kc][0], ahi[tl][kc][1],
                            ahi[tl][kc][2], ahi[tl][kc][3],
                            bhh_hi[kc][nt][0], bhh_hi[kc][nt][1]);
#pragma unroll
        for (int kc = 0; kc < 2; kc++)
#pragma unroll
            for (int nt = 0; nt < 4; nt++)
#pragma unroll
                for (int tl = 0; tl < TILES; tl++)
                    mma_acc(d0[tl][nt], d1[tl][nt], d2[tl][nt], d3[tl][nt],
                            alo[tl][kc][0], alo[tl][kc][1],
                            alo[tl][kc][2], alo[tl][kc][3],
                            bhh_hi[kc][nt][0], bhh_hi[kc][nt][1]);
#pragma unroll
        for (int kc = 0; kc < 2; kc++)
#pragma unroll
            for (int nt = 0; nt < 4; nt++)
#pragma unroll
                for (int tl = 0; tl < TILES; tl++)
                    mma_acc(d0[tl][nt], d1[tl][nt], d2[tl][nt], d3[tl][nt],
                            ahi[tl][kc][0], ahi[tl][kc][1],
                            ahi[tl][kc][2], ahi[tl][kc][3],
                            bhh_lo[kc][nt][0], bhh_lo[kc][nt][1]);

        // relu (fp32 exact) + D -> A (native layout identity), per tile
#pragma unroll
        for (int tl = 0; tl < TILES; tl++) {
#pragma unroll
            for (int nt = 0; nt < 4; nt++) {
                d0[tl][nt] = fmaxf(d0[tl][nt], 0.0f);
                d1[tl][nt] = fmaxf(d1[tl][nt], 0.0f);
                d2[tl][nt] = fmaxf(d2[tl][nt], 0.0f);
                d3[tl][nt] = fmaxf(d3[tl][nt], 0.0f);
            }
#pragma unroll
            for (int kc = 0; kc < 2; kc++) {
                const int u = 2 * kc, v = 2 * kc + 1;
                unsigned h;
                h = h2u(d0[tl][u], d1[tl][u]); ahi[tl][kc][0] = h;
                alo[tl][kc][0] = h2u(d0[tl][u] - h2lo(h), d1[tl][u] - h2hi(h));
                h = h2u(d2[tl][u], d3[tl][u]); ahi[tl][kc][1] = h;
                alo[tl][kc][1] = h2u(d2[tl][u] - h2lo(h), d3[tl][u] - h2hi(h));
                h = h2u(d0[tl][v], d1[tl][v]); ahi[tl][kc][2] = h;
                alo[tl][kc][2] = h2u(d0[tl][v] - h2lo(h), d1[tl][v] - h2hi(h));
                h = h2u(d2[tl][v], d3[tl][v]); ahi[tl][kc][3] = h;
                alo[tl][kc][3] = h2u(d2[tl][v] - h2lo(h), d3[tl][v] - h2hi(h));
            }
        }
    }

    // ---- FC head: d regs hold h_T at [gr / gr+8][8nt + 2c, 2c+1] ----
#pragma unroll
    for (int tl = 0; tl < TILES; tl++) {
        const int rA = rowbase + 16 * tl + gr;
        const int rB = rA + 8;
#pragma unroll
        for (int o = 0; o < NO; o++) {
            float accA = 0.f, accB = 0.f;
#pragma unroll
            for (int nt = 0; nt < 4; nt++) {
                const float fw0 = fc_w[o * NH + 8 * nt + 2 * c];
                const float fw1 = fc_w[o * NH + 8 * nt + 2 * c + 1];
                accA = fmaf(d0[tl][nt], fw0, fmaf(d1[tl][nt], fw1, accA));
                accB = fmaf(d2[tl][nt], fw0, fmaf(d3[tl][nt], fw1, accB));
            }
            accA += __shfl_xor_sync(0xffffffffu, accA, 1);
            accA += __shfl_xor_sync(0xffffffffu, accA, 2);
            accB += __shfl_xor_sync(0xffffffffu, accB, 1);
            accB += __shfl_xor_sync(0xffffffffu, accB, 2);
            if (c == 0) {
                out[rA * NO + o] = accA + fc_b[o];
                out[rB * NO + o] = accB + fc_b[o];
            }
        }
    }
}

extern "C" void kernel_launch(void* const* d_in, const int* in_sizes, int n_in,
                              void* d_out, int out_size) {
    const float* seq  = (const float*)d_in[0];
    const float* w_ih = (const float*)d_in[1];
    const float* w_hh = (const float*)d_in[2];
    const float* b_ih = (const float*)d_in[3];
    const float* b_hh = (const float*)d_in[4];
    const float* fc_w = (const float*)d_in[5];
    const float* fc_b = (const float*)d_in[6];
    float* out = (float*)d_out;

    rnn_mma_kernel<<<NBLOCKS, 32>>>(seq, w_ih, w_hh, b_ih, b_hh,
                                    fc_w, fc_b, out);
}

// round 15
// speedup vs baseline: 1.9818x; 1.9818x over previous
#include <cuda_runtime.h>
#include <cuda_fp16.h>

// Problem constants
#define NB 4096
#define NT 512
#define NC 4
#define NH 32
#define NO 3

// One block (64 threads, 2 warps) = one 16-row MMA tile.
// Warp w computes n-tiles {2w, 2w+1} (cols 16w..16w+15) = 16 MMAs/step.
// Peer k-chunk A-fragments exchanged through smem once per step.
#define ROWS_PER_BLOCK 16
#define NBLOCKS (NB / ROWS_PER_BLOCK)   // 256
#define NTHREADS 64

__device__ __forceinline__ unsigned h2u(float lo, float hi) {
    __half2 h = __floats2half2_rn(lo, hi);
    return *reinterpret_cast<unsigned*>(&h);
}
__device__ __forceinline__ float h2lo(unsigned u) {
    __half2 h = *reinterpret_cast<__half2*>(&u);
    return __low2float(h);
}
__device__ __forceinline__ float h2hi(unsigned u) {
    __half2 h = *reinterpret_cast<__half2*>(&u);
    return __high2float(h);
}

// D = A*B + D   (m16n8k16, f16 inputs, f32 accumulate)
__device__ __forceinline__ void mma_acc(float& d0, float& d1, float& d2, float& d3,
                                        unsigned a0, unsigned a1, unsigned a2, unsigned a3,
                                        unsigned b0, unsigned b1) {
    asm volatile(
        "mma.sync.aligned.m16n8k16.row.col.f32.f16.f16.f32 "
        "{%0,%1,%2,%3}, {%4,%5,%6,%7}, {%8,%9}, {%0,%1,%2,%3};"
        : "+f"(d0), "+f"(d1), "+f"(d2), "+f"(d3)
        : "r"(a0), "r"(a1), "r"(a2), "r"(a3), "r"(b0), "r"(b1));
}
// D = A*B  (C = 0)
__device__ __forceinline__ void mma_zro(float& d0, float& d1, float& d2, float& d3,
                                        unsigned a0, unsigned a1, unsigned a2, unsigned a3,
                                        unsigned b0, unsigned b1) {
    asm volatile(
        "mma.sync.aligned.m16n8k16.row.col.f32.f16.f16.f32 "
        "{%0,%1,%2,%3}, {%4,%5,%6,%7}, {%8,%9}, {%10,%10,%10,%10};"
        : "=f"(d0), "=f"(d1), "=f"(d2), "=f"(d3)
        : "r"(a0), "r"(a1), "r"(a2), "r"(a3), "r"(b0), "r"(b1), "f"(0.0f));
}

__global__ void __launch_bounds__(NTHREADS)
rnn_mma_kernel(const float* __restrict__ seq,
               const float* __restrict__ w_ih,
               const float* __restrict__ w_hh,
               const float* __restrict__ b_ih,
               const float* __restrict__ b_hh,
               const float* __restrict__ fc_w,
               const float* __restrict__ fc_b,
               float* __restrict__ out) {
    // Exchange buffers: [parity][warp][lane][8 regs] (32 B/lane, 16B-aligned)
    __shared__ unsigned xch[2][2][32][8];
    __shared__ float fcp[2][ROWS_PER_BLOCK][NO];   // FC partials per warp

    const int tid  = threadIdx.x;
    const int wid  = tid >> 5;           // warp 0/1: owns kc = wid
    const int peer = wid ^ 1;
    const int lane = tid & 31;
    const int gr   = lane >> 2;          // 0..7 row group
    const int c    = lane & 3;           // 0..3 col group
    const int rowbase = blockIdx.x * ROWS_PER_BLOCK;
    const int rA = rowbase + gr;
    const int rB = rA + 8;
    const bool lt2 = (c < 2);

    // ---- W_hh^T B-fragments for THIS warp's 2 n-tiles, all kc, hi/lo split ----
    unsigned bhh_hi[2][2][2], bhh_lo[2][2][2];   // [kc][lnt][frag]
#pragma unroll
    for (int kc = 0; kc < 2; kc++) {
#pragma unroll
        for (int lnt = 0; lnt < 2; lnt++) {
            const int n  = 8 * (2 * wid + lnt) + gr;
            const int k0 = 16 * kc + 2 * c;
            float w[4] = { w_hh[n * NH + k0],     w_hh[n * NH + k0 + 1],
                           w_hh[n * NH + k0 + 8], w_hh[n * NH + k0 + 9] };
            float wh[4], wl[4];
#pragma unroll
            for (int i = 0; i < 4; i++) {
                wh[i] = __half2float(__float2half_rn(w[i]));
                wl[i] = w[i] - wh[i];
            }
            bhh_hi[kc][lnt][0] = h2u(wh[0], wh[1]);
            bhh_hi[kc][lnt][1] = h2u(wh[2], wh[3]);
            bhh_lo[kc][lnt][0] = h2u(wl[0], wl[1]);
            bhh_lo[kc][lnt][1] = h2u(wl[2], wl[3]);
        }
    }

    // ---- x_proj B-fragments (k-rows 0..3 = w_ih^T, k-row 4 = bias) ----
    unsigned bih_hi[2], bih_lo[2];
#pragma unroll
    for (int lnt = 0; lnt < 2; lnt++) {
        const int n = 8 * (2 * wid + lnt) + gr;
        float v[2];
#pragma unroll
        for (int i = 0; i < 2; i++) {
            const int k = 2 * c + i;
            v[i] = (k < NC) ? w_ih[n * NC + k]
                            : ((k == NC) ? (b_ih[n] + b_hh[n]) : 0.0f);
        }
        const float vh0 = __half2float(__float2half_rn(v[0]));
        const float vh1 = __half2float(__float2half_rn(v[1]));
        bih_hi[lnt] = h2u(vh0, vh1);
        bih_lo[lnt] = h2u(v[0] - vh0, v[1] - vh1);
    }
    const unsigned zero_b = 0u;
    const unsigned aconst = (c == 2) ? h2u(1.0f, 0.0f) : 0u;

    // seq: both warps load the same rows (L1 broadcast). 2-step prefetch.
    const float2* pA = reinterpret_cast<const float2*>(seq + (size_t)rA * (NT * NC));
    const float2* pB = reinterpret_cast<const float2*>(seq + (size_t)rB * (NT * NC));
    const float2 f2z = make_float2(0.f, 0.f);
    float2 sA0 = lt2 ? pA[c]     : f2z;
    float2 sB0 = lt2 ? pB[c]     : f2z;
    float2 sA1 = lt2 ? pA[2 + c] : f2z;
    float2 sB1 = lt2 ? pB[2 + c] : f2z;

    // A-fragments: own kc (= wid) kept in regs; peer kc loaded from smem.
    unsigned ahi_o[4] = {0u,0u,0u,0u}, alo_o[4] = {0u,0u,0u,0u};
    unsigned ahi_p[4] = {0u,0u,0u,0u}, alo_p[4] = {0u,0u,0u,0u};
    float d0[2], d1[2], d2[2], d3[2];   // accumulators for 2 local n-tiles

    for (int t = 0; t < NT; t++) {
        const int par = t & 1;
        const float2 cA = sA0;  sA0 = sA1;
        const float2 cB = sB0;  sB0 = sB1;
        const int tn = (t + 2 < NT) ? (t + 2) : (NT - 1);
        sA1 = lt2 ? pA[2 * tn + c] : f2z;
        sB1 = lt2 ? pB[2 * tn + c] : f2z;
        const unsigned as0 = lt2 ? h2u(cA.x, cA.y) : aconst;
        const unsigned as1 = lt2 ? h2u(cB.x, cB.y) : aconst;

        // --- peer-independent MMAs first (10): hide the exchange latency ---
#pragma unroll
        for (int lnt = 0; lnt < 2; lnt++) {
            mma_zro(d0[lnt], d1[lnt], d2[lnt], d3[lnt],
                    as0, as1, 0u, 0u, bih_hi[lnt], zero_b);
            mma_acc(d0[lnt], d1[lnt], d2[lnt], d3[lnt],
                    as0, as1, 0u, 0u, bih_lo[lnt], zero_b);
            mma_acc(d0[lnt], d1[lnt], d2[lnt], d3[lnt],
                    ahi_o[0], ahi_o[1], ahi_o[2], ahi_o[3],
                    bhh_hi[wid][lnt][0], bhh_hi[wid][lnt][1]);
            mma_acc(d0[lnt], d1[lnt], d2[lnt], d3[lnt],
                    alo_o[0], alo_o[1], alo_o[2], alo_o[3],
                    bhh_hi[wid][lnt][0], bhh_hi[wid][lnt][1]);
            mma_acc(d0[lnt], d1[lnt], d2[lnt], d3[lnt],
                    ahi_o[0], ahi_o[1], ahi_o[2], ahi_o[3],
                    bhh_lo[wid][lnt][0], bhh_lo[wid][lnt][1]);
        }
        // --- peer-dependent MMAs (6) ---
#pragma unroll
        for (int lnt = 0; lnt < 2; lnt++) {
            mma_acc(d0[lnt], d1[lnt], d2[lnt], d3[lnt],
                    ahi_p[0], ahi_p[1], ahi_p[2], ahi_p[3],
                    bhh_hi[peer][lnt][0], bhh_hi[peer][lnt][1]);
            mma_acc(d0[lnt], d1[lnt], d2[lnt], d3[lnt],
                    alo_p[0], alo_p[1], alo_p[2], alo_p[3],
                    bhh_hi[peer][lnt][0], bhh_hi[peer][lnt][1]);
            mma_acc(d0[lnt], d1[lnt], d2[lnt], d3[lnt],
                    ahi_p[0], ahi_p[1], ahi_p[2], ahi_p[3],
                    bhh_lo[peer][lnt][0], bhh_lo[peer][lnt][1]);
        }

        // relu (fp32 exact)
#pragma unroll
        for (int lnt = 0; lnt < 2; lnt++) {
            d0[lnt] = fmaxf(d0[lnt], 0.0f);
            d1[lnt] = fmaxf(d1[lnt], 0.0f);
            d2[lnt] = fmaxf(d2[lnt], 0.0f);
            d3[lnt] = fmaxf(d3[lnt], 0.0f);
        }

        // D -> A (native layout identity): local n-tiles ARE k-chunk kc=wid.
        unsigned h;
        h = h2u(d0[0], d1[0]); ahi_o[0] = h;
        alo_o[0] = h2u(d0[0] - h2lo(h), d1[0] - h2hi(h));
        h = h2u(d2[0], d3[0]); ahi_o[1] = h;
        alo_o[1] = h2u(d2[0] - h2lo(h), d3[0] - h2hi(h));
        h = h2u(d0[1], d1[1]); ahi_o[2] = h;
        alo_o[2] = h2u(d0[1] - h2lo(h), d1[1] - h2hi(h));
        h = h2u(d2[1], d3[1]); ahi_o[3] = h;
        alo_o[3] = h2u(d2[1] - h2lo(h), d3[1] - h2hi(h));

        // exchange: publish own kc frags, fetch peer kc frags (dbl-buffered)
        uint4* dst = reinterpret_cast<uint4*>(&xch[par][wid][lane][0]);
        dst[0] = make_uint4(ahi_o[0], ahi_o[1], ahi_o[2], ahi_o[3]);
        dst[1] = make_uint4(alo_o[0], alo_o[1], alo_o[2], alo_o[3]);
        __syncthreads();
        const uint4* src = reinterpret_cast<const uint4*>(&xch[par][peer][lane][0]);
        const uint4 phi = src[0];
        const uint4 plo = src[1];
        ahi_p[0] = phi.x; ahi_p[1] = phi.y; ahi_p[2] = phi.z; ahi_p[3] = phi.w;
        alo_p[0] = plo.x; alo_p[1] = plo.y; alo_p[2] = plo.z; alo_p[3] = plo.w;
    }

    // ---- FC head: warp w holds h cols {16w + 8*lnt + 2c, +1} for rows gr, gr+8 ----
#pragma unroll
    for (int o = 0; o < NO; o++) {
        float accA = 0.f, accB = 0.f;
#pragma unroll
        for (int lnt = 0; lnt < 2; lnt++) {
            const int nb = 16 * wid + 8 * lnt + 2 * c;
            const float fw0 = fc_w[o * NH + nb];
            const float fw1 = fc_w[o * NH + nb + 1];
            accA = fmaf(d0[lnt], fw0, fmaf(d1[lnt], fw1, accA));
            accB = fmaf(d2[lnt], fw0, fmaf(d3[lnt], fw1, accB));
        }
        accA += __shfl_xor_sync(0xffffffffu, accA, 1);
        accA += __shfl_xor_sync(0xffffffffu, accA, 2);
        accB += __shfl_xor_sync(0xffffffffu, accB, 1);
        accB += __shfl_xor_sync(0xffffffffu, accB, 2);
        if (c == 0) {
            fcp[wid][gr][o]     = accA;
            fcp[wid][gr + 8][o] = accB;
        }
    }
    __syncthreads();
    if (tid < ROWS_PER_BLOCK * NO) {
        const int row = tid / NO;
        const int o   = tid % NO;
        out[(rowbase + row) * NO + o] = fcp[0][row][o] + fcp[1][row][o] + fc_b[o];
    }
}

extern "C" void kernel_launch(void* const* d_in, const int* in_sizes, int n_in,
                              void* d_out, int out_size) {
    const float* seq  = (const float*)d_in[0];
    const float* w_ih = (const float*)d_in[1];
    const float* w_hh = (const float*)d_in[2];
    const float* b_ih = (const float*)d_in[3];
    const float* b_hh = (const float*)d_in[4];
    const float* fc_w = (const float*)d_in[5];
    const float* fc_b = (const float*)d_in[6];
    float* out = (float*)d_out;

    rnn_mma_kernel<<<NBLOCKS, NTHREADS>>>(seq, w_ih, w_hh, b_ih, b_hh,
                                          fc_w, fc_b, out);
}